// round 4
// baseline (speedup 1.0000x reference)
#include <cuda_runtime.h>
#include <cuda_bf16.h>
#include <cstdint>
#include <cstddef>

// Problem constants
#define T_TOK   4096      // B*S
#define DDIM    1024
#define HDIM    4096
#define NEXP    8
#define CAP     2048
#define NSLOT   (T_TOK*2) // K=2

// GEMM tiling
#define BM 128
#define BN 128
#define BKT 16
#define ASTRIDE 20    // padded A row stride (floats), 16B-aligned chunks, conflict-free
#define BSTRIDE 132   // padded B row stride (floats)

// ---------------- device scratch (allocation-free rule: device globals) ----
__device__ float g_hbuf[(size_t)NEXP * CAP * HDIM];   // 256 MB intermediate h (tf32-rounded)
__device__ float g_w1t[(size_t)NEXP * DDIM * HDIM];   // 128 MB tf32-rounded w1
__device__ float g_w2t[(size_t)NEXP * HDIM * DDIM];   // 128 MB tf32-rounded w2
__device__ float g_xt[(size_t)T_TOK * DDIM];          // 16 MB  tf32-rounded x
__device__ int   g_eidx[NSLOT];
__device__ float g_gate[NSLOT];
__device__ int   g_arow[NEXP * CAP];    // gather offsets (token*DDIM) per expert row
__device__ int   g_rowinfo[NEXP * CAP]; // slot index per expert row
__device__ int   g_counts[NEXP];
__device__ float g_partial[512 * NEXP]; // per-block router prob partial sums

// ---------------- small PTX helpers ----------------
__device__ __forceinline__ void cp_async16(void* smem, const void* gmem) {
    uint32_t s = (uint32_t)__cvta_generic_to_shared(smem);
    asm volatile("cp.async.cg.shared.global [%0], [%1], 16;\n" :: "r"(s), "l"(gmem));
}
__device__ __forceinline__ void cp_commit() { asm volatile("cp.async.commit_group;\n"); }
__device__ __forceinline__ void cp_wait1() { asm volatile("cp.async.wait_group 1;\n"); }
__device__ __forceinline__ void cp_wait0() { asm volatile("cp.async.wait_group 0;\n"); }

__device__ __forceinline__ float f2tf32f(float v) {
    uint32_t r;
    asm("cvt.rna.tf32.f32 %0, %1;" : "=r"(r) : "f"(v));
    return __uint_as_float(r);
}
__device__ __forceinline__ void mma_tf32(float* d, const uint32_t* a, const uint32_t* b) {
    asm volatile(
        "mma.sync.aligned.m16n8k8.row.col.f32.tf32.tf32.f32 "
        "{%0,%1,%2,%3}, {%4,%5,%6,%7}, {%8,%9}, {%0,%1,%2,%3};\n"
        : "+f"(d[0]), "+f"(d[1]), "+f"(d[2]), "+f"(d[3])
        : "r"(a[0]), "r"(a[1]), "r"(a[2]), "r"(a[3]), "r"(b[0]), "r"(b[1]));
}
__device__ __forceinline__ float gelu_exact(float v) {
    return 0.5f * v * (1.0f + erff(v * 0.70710678118654752440f));
}

// ---------------- prep: round operands to tf32 once ----------------
__global__ __launch_bounds__(256) void cvt_kernel(const float4* __restrict__ src,
                                                  float4* __restrict__ dst, int n4)
{
    int stride = gridDim.x * blockDim.x;
    for (int i = blockIdx.x * blockDim.x + threadIdx.x; i < n4; i += stride) {
        float4 v = src[i];
        v.x = f2tf32f(v.x); v.y = f2tf32f(v.y);
        v.z = f2tf32f(v.z); v.w = f2tf32f(v.w);
        dst[i] = v;
    }
}

// ---------------- router: logits -> softmax -> top2 -> gates ----------------
__global__ __launch_bounds__(256) void router_kernel(
    const float* __restrict__ x, const float* __restrict__ rw)
{
    __shared__ float srw[NEXP * DDIM];       // 32 KB
    __shared__ float sp[8][NEXP];
    int tid = threadIdx.x;
    for (int i = tid; i < NEXP * DDIM; i += 256) srw[i] = rw[i];
    __syncthreads();

    int warp = tid >> 5, lane = tid & 31;
    int t = blockIdx.x * 8 + warp;

    float acc[NEXP];
#pragma unroll
    for (int e = 0; e < NEXP; e++) acc[e] = 0.f;

    const float* xr = x + (size_t)t * DDIM;
    for (int d = lane; d < DDIM; d += 32) {
        float xv = xr[d];
#pragma unroll
        for (int e = 0; e < NEXP; e++) acc[e] += xv * srw[e * DDIM + d];
    }
#pragma unroll
    for (int off = 16; off; off >>= 1) {
#pragma unroll
        for (int e = 0; e < NEXP; e++)
            acc[e] += __shfl_down_sync(0xffffffffu, acc[e], off);
    }
    if (lane == 0) {
        float m = acc[0];
#pragma unroll
        for (int e = 1; e < NEXP; e++) m = fmaxf(m, acc[e]);
        float p[NEXP], s = 0.f;
#pragma unroll
        for (int e = 0; e < NEXP; e++) { p[e] = expf(acc[e] - m); s += p[e]; }
        float inv = 1.0f / s;
#pragma unroll
        for (int e = 0; e < NEXP; e++) p[e] *= inv;

        int e1 = 0;
#pragma unroll
        for (int e = 1; e < NEXP; e++) if (p[e] > p[e1]) e1 = e;
        int e2 = (e1 == 0) ? 1 : 0;
#pragma unroll
        for (int e = 0; e < NEXP; e++) if (e != e1 && p[e] > p[e2]) e2 = e;

        float denom = p[e1] + p[e2];
        g_eidx[2 * t]     = e1;  g_gate[2 * t]     = p[e1] / denom;
        g_eidx[2 * t + 1] = e2;  g_gate[2 * t + 1] = p[e2] / denom;
#pragma unroll
        for (int e = 0; e < NEXP; e++) sp[warp][e] = p[e];
    }
    __syncthreads();
    if (tid < NEXP) {
        float s = 0.f;
#pragma unroll
        for (int w = 0; w < 8; w++) s += sp[w][tid];
        g_partial[blockIdx.x * NEXP + tid] = s;
    }
}

// ---------------- deterministic capacity scan (1 block) ----------------
__global__ __launch_bounds__(256) void scan_kernel(float* __restrict__ lb_out)
{
    __shared__ int cnt[256][NEXP];
    __shared__ int tot[NEXP];
    int tid = threadIdx.x;

    for (int i = tid; i < NEXP * CAP; i += 256) g_arow[i] = 0;

    int base = tid * 32;
    int lc[NEXP];
#pragma unroll
    for (int e = 0; e < NEXP; e++) lc[e] = 0;
    for (int i = 0; i < 32; i++) lc[g_eidx[base + i]]++;
#pragma unroll
    for (int e = 0; e < NEXP; e++) cnt[tid][e] = lc[e];
    __syncthreads();

    if (tid < NEXP) {
        int s = 0;
        for (int j = 0; j < 256; j++) { int v = cnt[j][tid]; cnt[j][tid] = s; s += v; }
        tot[tid] = s;
        g_counts[tid] = (s < CAP) ? s : CAP;
    }
    __syncthreads();

    int run[NEXP];
#pragma unroll
    for (int e = 0; e < NEXP; e++) run[e] = cnt[tid][e];
    for (int i = 0; i < 32; i++) {
        int slot = base + i;
        int e = g_eidx[slot];
        int pos = run[e]++;
        if (pos < CAP) {
            g_rowinfo[e * CAP + pos] = slot;
            g_arow[e * CAP + pos] = (slot >> 1) * DDIM;
        }
    }

    if (tid == 0) {
        float lb = 0.f;
        for (int e = 0; e < NEXP; e++) {
            float ps = 0.f;
            for (int b = 0; b < 512; b++) ps += g_partial[b * NEXP + e];
            lb += (ps / (float)T_TOK) * ((float)tot[e] / (float)NSLOT);
        }
        *lb_out = lb * (float)NEXP;
    }
}

// ---------------- tf32 GEMM (operands pre-rounded; no inner-loop cvt) ----
// EPI 0 = gather-A + GELU->hbuf (tf32-rounded), EPI 1 = scatter-add out
template <int EPI>
__global__ __launch_bounds__(256, 2) void moe_gemm(
    const float* __restrict__ Bbase,  // g_w1t or g_w2t (E x K x N)
    const float* __restrict__ bias,   // b1 or b2 (E x N)
    float* __restrict__ outp,         // EPI1: out base
    int Kdim, int Ncols)
{
    __shared__ float As[2][BM * ASTRIDE];
    __shared__ float Bs[2][BKT * BSTRIDE];
    __shared__ const float* Arows[BM];

    const int e = blockIdx.z;
    const int m0blk = blockIdx.y * BM;
    const int n0blk = blockIdx.x * BN;
    const int tid = threadIdx.x;

    if (tid < BM) {
        int gm = m0blk + tid;
        const float* p;
        if (EPI == 0) p = g_xt + g_arow[e * CAP + gm];
        else          p = g_hbuf + (size_t)(e * CAP + gm) * Kdim;
        Arows[tid] = p;
    }
    const float* Bexp = Bbase + (size_t)e * Kdim * Ncols;
    const float* brow = bias + e * Ncols;
    __syncthreads();

    const int warp = tid >> 5, lane = tid & 31;
    const int wm = (warp >> 2) * 64;
    const int wn = (warp & 3) * 32;
    const int grp = lane >> 2, qid = lane & 3;

    float acc[4][4][4];
#pragma unroll
    for (int mi = 0; mi < 4; mi++)
#pragma unroll
        for (int ni = 0; ni < 4; ni++)
#pragma unroll
            for (int j = 0; j < 4; j++) acc[mi][ni][j] = 0.f;

    const int nk = Kdim / BKT;

    auto issue = [&](int buf, int kt) {
        int k0 = kt * BKT;
#pragma unroll
        for (int i = 0; i < 2; i++) {                 // A: 512 x 16B chunks
            int c = i * 256 + tid;
            int r = c >> 2;
            int kc = (c & 3) * 4;
            cp_async16(&As[buf][r * ASTRIDE + kc], Arows[r] + k0 + kc);
        }
#pragma unroll
        for (int i = 0; i < 2; i++) {                 // B: 512 x 16B chunks
            int c = i * 256 + tid;
            int kr = c >> 5;
            int cc = (c & 31) * 4;
            cp_async16(&Bs[buf][kr * BSTRIDE + cc],
                       Bexp + (size_t)(k0 + kr) * Ncols + n0blk + cc);
        }
        cp_commit();
    };

    issue(0, 0);
    for (int kt = 0; kt < nk; ++kt) {
        int cur = kt & 1;
        if (kt + 1 < nk) { issue(cur ^ 1, kt + 1); cp_wait1(); }
        else             { cp_wait0(); }
        __syncthreads();

        const uint32_t* As32 = reinterpret_cast<const uint32_t*>(As[cur]);
        const uint32_t* Bs32 = reinterpret_cast<const uint32_t*>(Bs[cur]);

#pragma unroll
        for (int kk = 0; kk < BKT; kk += 8) {
            uint32_t afr[4][4];
#pragma unroll
            for (int mi = 0; mi < 4; mi++) {
                int r = wm + mi * 16 + grp;
                const uint32_t* a0 = &As32[r * ASTRIDE + kk + qid];
                const uint32_t* a1 = &As32[(r + 8) * ASTRIDE + kk + qid];
                afr[mi][0] = a0[0];
                afr[mi][1] = a1[0];
                afr[mi][2] = a0[4];
                afr[mi][3] = a1[4];
            }
            uint32_t bfr[4][2];
#pragma unroll
            for (int ni = 0; ni < 4; ni++) {
                int ccol = wn + ni * 8 + grp;
                bfr[ni][0] = Bs32[(kk + qid) * BSTRIDE + ccol];
                bfr[ni][1] = Bs32[(kk + qid + 4) * BSTRIDE + ccol];
            }
#pragma unroll
            for (int mi = 0; mi < 4; mi++)
#pragma unroll
                for (int ni = 0; ni < 4; ni++)
                    mma_tf32(acc[mi][ni], afr[mi], bfr[ni]);
        }
        __syncthreads();
    }

    // ---------------- epilogue ----------------
    if (EPI == 0) {
#pragma unroll
        for (int mi = 0; mi < 4; mi++) {
            int r0 = m0blk + wm + mi * 16 + grp;
            int r1 = r0 + 8;
#pragma unroll
            for (int ni = 0; ni < 4; ni++) {
                int c0 = n0blk + wn + ni * 8 + qid * 2;
                float b0  = brow[c0];
                float b1v = brow[c0 + 1];
                size_t o0 = (size_t)(e * CAP + r0) * Ncols + c0;
                size_t o1 = (size_t)(e * CAP + r1) * Ncols + c0;
                // store tf32-rounded so GEMM2 needs no conversion (bit-identical)
                g_hbuf[o0]     = f2tf32f(gelu_exact(acc[mi][ni][0] + b0));
                g_hbuf[o0 + 1] = f2tf32f(gelu_exact(acc[mi][ni][1] + b1v));
                g_hbuf[o1]     = f2tf32f(gelu_exact(acc[mi][ni][2] + b0));
                g_hbuf[o1 + 1] = f2tf32f(gelu_exact(acc[mi][ni][3] + b1v));
            }
        }
    } else {
        int cnt = g_counts[e];
#pragma unroll
        for (int mi = 0; mi < 4; mi++) {
            int r0 = m0blk + wm + mi * 16 + grp;
            int r1 = r0 + 8;
            int slot0 = (r0 < cnt) ? g_rowinfo[e * CAP + r0] : -1;
            int slot1 = (r1 < cnt) ? g_rowinfo[e * CAP + r1] : -1;
            float gf0 = (slot0 >= 0) ? g_gate[slot0] : 0.f;
            float gf1 = (slot1 >= 0) ? g_gate[slot1] : 0.f;
            int tok0 = (slot0 >= 0) ? (slot0 >> 1) : 0;
            int tok1 = (slot1 >= 0) ? (slot1 >> 1) : 0;
#pragma unroll
            for (int ni = 0; ni < 4; ni++) {
                int c0 = n0blk + wn + ni * 8 + qid * 2;
                float b0  = brow[c0];
                float b1v = brow[c0 + 1];
                if (slot0 >= 0) {
                    atomicAdd(&outp[(size_t)tok0 * DDIM + c0],     gf0 * (acc[mi][ni][0] + b0));
                    atomicAdd(&outp[(size_t)tok0 * DDIM + c0 + 1], gf0 * (acc[mi][ni][1] + b1v));
                }
                if (slot1 >= 0) {
                    atomicAdd(&outp[(size_t)tok1 * DDIM + c0],     gf1 * (acc[mi][ni][2] + b0));
                    atomicAdd(&outp[(size_t)tok1 * DDIM + c0 + 1], gf1 * (acc[mi][ni][3] + b1v));
                }
            }
        }
    }
}

// ---------------- launch ----------------
extern "C" void kernel_launch(void* const* d_in, const int* in_sizes, int n_in,
                              void* d_out, int out_size)
{
    (void)in_sizes; (void)n_in; (void)out_size;
    const float* x   = (const float*)d_in[0];
    const float* rw  = (const float*)d_in[1];
    const float* w1  = (const float*)d_in[2];
    const float* b1  = (const float*)d_in[3];
    const float* w2  = (const float*)d_in[4];
    const float* b2  = (const float*)d_in[5];
    float* out = (float*)d_out;

    cudaMemsetAsync(out, 0, (size_t)T_TOK * DDIM * sizeof(float));

    // resolve device-global addresses once (host-side, capture-safe)
    static float *w1t_p = nullptr, *w2t_p = nullptr, *xt_p = nullptr;
    if (!w1t_p) {
        cudaGetSymbolAddress((void**)&w1t_p, g_w1t);
        cudaGetSymbolAddress((void**)&w2t_p, g_w2t);
        cudaGetSymbolAddress((void**)&xt_p,  g_xt);
    }

    const int n4_w = (NEXP * DDIM * HDIM) / 4;   // 8.39M float4
    const int n4_x = (T_TOK * DDIM) / 4;         // 1M float4
    cvt_kernel<<<2048, 256>>>((const float4*)w1, (float4*)w1t_p, n4_w);
    cvt_kernel<<<2048, 256>>>((const float4*)w2, (float4*)w2t_p, n4_w);
    cvt_kernel<<<512,  256>>>((const float4*)x,  (float4*)xt_p,  n4_x);

    router_kernel<<<T_TOK / 8, 256>>>(x, rw);
    scan_kernel<<<1, 256>>>(out + (size_t)T_TOK * DDIM);

    dim3 g1(HDIM / BN, CAP / BM, NEXP);   // 32 x 16 x 8
    moe_gemm<0><<<g1, 256>>>(w1t_p, b1, nullptr, DDIM, HDIM);

    dim3 g2(DDIM / BN, CAP / BM, NEXP);   // 8 x 16 x 8
    moe_gemm<1><<<g2, 256>>>(w2t_p, b2, out, HDIM, DDIM);
}

// round 6
// speedup vs baseline: 1.2596x; 1.2596x over previous
#include <cuda_runtime.h>
#include <cuda_fp16.h>
#include <cstdint>
#include <cstddef>

// ---------------- problem constants ----------------
#define T_TOK 4096
#define DDIM  1024
#define HDIM  4096
#define NEXP  8
#define CAP   2048
#define NSLOT (T_TOK*2)

// ---------------- GEMM tiling (fp16 legacy mma) ----------------
#define BM 128
#define BN 128
#define BKH 32          // halves of K per stage (two m16n8k16 steps)
#define ROWW 20         // words (b32) per smem row: 16 data + 4 pad -> conflict-free
#define ROWH 40         // halves per smem row

// ---------------- device scratch ----------------
__device__ __half g_hbufh[(size_t)NEXP*CAP*HDIM];  // 64MB gelu(h) in half
__device__ float  g_obuf [(size_t)NEXP*CAP*DDIM];  // 64MB expert outputs (pre-gate)
__device__ __half g_w1h  [(size_t)NEXP*DDIM*HDIM]; // w1^T [E][H][D] half
__device__ __half g_w2h  [(size_t)NEXP*HDIM*DDIM]; // w2^T [E][D][H] half
__device__ __half g_xh   [(size_t)T_TOK*DDIM];     // x in half
__device__ int    g_eidx[NSLOT];
__device__ float  g_gate[NSLOT];
__device__ int    g_arow[NEXP*CAP];
__device__ int    g_slotpos[NSLOT];
__device__ float  g_partial[512*NEXP];

// ---------------- helpers ----------------
__device__ __forceinline__ uint32_t smem_u32(const void* p){
    uint32_t a;
    asm("{ .reg .u64 t; cvta.to.shared.u64 t, %1; cvt.u32.u64 %0, t; }" : "=r"(a) : "l"(p));
    return a;
}
__device__ __forceinline__ void cp_async16s(uint32_t s, const void* g) {
    asm volatile("cp.async.cg.shared.global [%0], [%1], 16;\n" :: "r"(s), "l"(g));
}
__device__ __forceinline__ void cp_commit() { asm volatile("cp.async.commit_group;\n"); }
__device__ __forceinline__ void cp_wait1()  { asm volatile("cp.async.wait_group 1;\n"); }
__device__ __forceinline__ void cp_wait0()  { asm volatile("cp.async.wait_group 0;\n"); }

__device__ __forceinline__ void mma_f16(float* d, const uint32_t* a, const uint32_t* b) {
    asm volatile(
        "mma.sync.aligned.m16n8k16.row.col.f32.f16.f16.f32 "
        "{%0,%1,%2,%3}, {%4,%5,%6,%7}, {%8,%9}, {%0,%1,%2,%3};\n"
        : "+f"(d[0]), "+f"(d[1]), "+f"(d[2]), "+f"(d[3])
        : "r"(a[0]), "r"(a[1]), "r"(a[2]), "r"(a[3]), "r"(b[0]), "r"(b[1]));
}
__device__ __forceinline__ float gelu_exact(float v) {
    return 0.5f * v * (1.0f + erff(v * 0.70710678118654752440f));
}

// ---------------- prep: cvt / transpose to half ----------------
__global__ __launch_bounds__(256) void cvt_h(const float2* __restrict__ src,
                                             __half2* __restrict__ dst, int n2)
{
    int stride = gridDim.x * blockDim.x;
    for (int i = blockIdx.x * blockDim.x + threadIdx.x; i < n2; i += stride) {
        float2 v = src[i];
        dst[i] = __floats2half2_rn(v.x, v.y);
    }
}

// src [e][R][C] fp32 -> dst [e][C][R] half
__global__ __launch_bounds__(256) void transpose_h(const float* __restrict__ src,
                                                   __half* __restrict__ dst, int R, int C)
{
    __shared__ float tile[32][33];
    int e = blockIdx.z;
    int r0 = blockIdx.y * 32, c0 = blockIdx.x * 32;
    const float* s = src + (size_t)e * R * C;
    __half* d = dst + (size_t)e * R * C;
    for (int i = threadIdx.y; i < 32; i += 8)
        tile[i][threadIdx.x] = s[(size_t)(r0 + i) * C + c0 + threadIdx.x];
    __syncthreads();
    for (int i = threadIdx.y; i < 32; i += 8)
        d[(size_t)(c0 + i) * R + r0 + threadIdx.x] = __float2half_rn(tile[threadIdx.x][i]);
}

// ---------------- router ----------------
__global__ __launch_bounds__(256) void router_kernel(
    const float* __restrict__ x, const float* __restrict__ rw)
{
    __shared__ float srw[NEXP * DDIM];
    __shared__ float sp[8][NEXP];
    int tid = threadIdx.x;
    for (int i = tid; i < NEXP * DDIM; i += 256) srw[i] = rw[i];
    __syncthreads();

    int warp = tid >> 5, lane = tid & 31;
    int t = blockIdx.x * 8 + warp;

    float acc[NEXP];
#pragma unroll
    for (int e = 0; e < NEXP; e++) acc[e] = 0.f;
    const float* xr = x + (size_t)t * DDIM;
    for (int d = lane; d < DDIM; d += 32) {
        float xv = xr[d];
#pragma unroll
        for (int e = 0; e < NEXP; e++) acc[e] += xv * srw[e * DDIM + d];
    }
#pragma unroll
    for (int off = 16; off; off >>= 1)
#pragma unroll
        for (int e = 0; e < NEXP; e++)
            acc[e] += __shfl_down_sync(0xffffffffu, acc[e], off);

    if (lane == 0) {
        float m = acc[0];
#pragma unroll
        for (int e = 1; e < NEXP; e++) m = fmaxf(m, acc[e]);
        float p[NEXP], s = 0.f;
#pragma unroll
        for (int e = 0; e < NEXP; e++) { p[e] = expf(acc[e] - m); s += p[e]; }
        float inv = 1.0f / s;
#pragma unroll
        for (int e = 0; e < NEXP; e++) p[e] *= inv;

        int e1 = 0;
#pragma unroll
        for (int e = 1; e < NEXP; e++) if (p[e] > p[e1]) e1 = e;
        int e2 = (e1 == 0) ? 1 : 0;
#pragma unroll
        for (int e = 0; e < NEXP; e++) if (e != e1 && p[e] > p[e2]) e2 = e;

        float denom = p[e1] + p[e2];
        g_eidx[2 * t]     = e1;  g_gate[2 * t]     = p[e1] / denom;
        g_eidx[2 * t + 1] = e2;  g_gate[2 * t + 1] = p[e2] / denom;
#pragma unroll
        for (int e = 0; e < NEXP; e++) sp[warp][e] = p[e];
    }
    __syncthreads();
    if (tid < NEXP) {
        float s = 0.f;
#pragma unroll
        for (int w = 0; w < 8; w++) s += sp[w][tid];
        g_partial[blockIdx.x * NEXP + tid] = s;
    }
}

// ---------------- deterministic capacity scan ----------------
__global__ __launch_bounds__(256) void scan_kernel(float* __restrict__ lb_out)
{
    __shared__ int cnt[256][NEXP];
    __shared__ int tot[NEXP];
    int tid = threadIdx.x;

    for (int i = tid; i < NEXP * CAP; i += 256) g_arow[i] = 0;

    int base = tid * 32;
    int lc[NEXP];
#pragma unroll
    for (int e = 0; e < NEXP; e++) lc[e] = 0;
    for (int i = 0; i < 32; i++) lc[g_eidx[base + i]]++;
#pragma unroll
    for (int e = 0; e < NEXP; e++) cnt[tid][e] = lc[e];
    __syncthreads();

    if (tid < NEXP) {
        int s = 0;
        for (int j = 0; j < 256; j++) { int v = cnt[j][tid]; cnt[j][tid] = s; s += v; }
        tot[tid] = s;
    }
    __syncthreads();

    int run[NEXP];
#pragma unroll
    for (int e = 0; e < NEXP; e++) run[e] = cnt[tid][e];
    for (int i = 0; i < 32; i++) {
        int slot = base + i;
        int e = g_eidx[slot];
        int pos = run[e]++;
        if (pos < CAP) {
            g_arow[e * CAP + pos] = (slot >> 1) * DDIM;
            g_slotpos[slot] = e * CAP + pos;
        } else {
            g_slotpos[slot] = -1;
        }
    }

    if (tid == 0) {
        float lb = 0.f;
        for (int e = 0; e < NEXP; e++) {
            float ps = 0.f;
            for (int b = 0; b < 512; b++) ps += g_partial[b * NEXP + e];
            lb += (ps / (float)T_TOK) * ((float)tot[e] / (float)NSLOT);
        }
        *lb_out = lb * (float)NEXP;
    }
}

// ---------------- fp16 mma GEMM ----------------
// EPI 0: A = gathered x rows (half), B = w1^T, epi = bias+gelu -> g_hbufh (half)
// EPI 1: A = hbufh rows,            B = w2^T, epi = bias      -> g_obuf (fp32)
template <int EPI>
__global__ __launch_bounds__(256, 2) void moe_gemm_h(
    const __half* __restrict__ Bw, const float* __restrict__ bias,
    int Kdim, int Ncols)
{
    __shared__ __align__(16) __half As[2][BM * ROWH];  // 10KB each
    __shared__ __align__(16) __half Bs[2][BM * ROWH];
    __shared__ const __half* Arows[BM];

    const int e = blockIdx.z;
    const int m0blk = blockIdx.y * BM;
    const int n0blk = blockIdx.x * BN;
    const int tid = threadIdx.x;

    if (tid < BM) {
        int gm = m0blk + tid;
        if (EPI == 0) Arows[tid] = g_xh + g_arow[e * CAP + gm];
        else          Arows[tid] = g_hbufh + (size_t)(e * CAP + gm) * Kdim;
    }
    const __half* Bexp = Bw + (size_t)e * Ncols * Kdim;
    const float* brow = bias + e * Ncols;
    __syncthreads();

    const int warp = tid >> 5, lane = tid & 31;
    const int wm = (warp >> 2) * 64;
    const int wn = (warp & 3) * 32;
    const int grp = lane >> 2, qid = lane & 3;

    float acc[4][4][4];
#pragma unroll
    for (int mi = 0; mi < 4; mi++)
#pragma unroll
        for (int ni = 0; ni < 4; ni++)
#pragma unroll
            for (int j = 0; j < 4; j++) acc[mi][ni][j] = 0.f;

    const int nk = Kdim / BKH;

    auto issue = [&](int buf, int kt) {
        const int ko = kt * BKH;
        uint32_t ab = smem_u32(&As[buf][0]);
        uint32_t bb = smem_u32(&Bs[buf][0]);
        // 512 chunks of 16B per matrix; 2 chunks per thread each
#pragma unroll
        for (int i = 0; i < 2; i++) {
            int c = i * 256 + tid;
            int row = c >> 2, ch = c & 3;
            cp_async16s(ab + row * 80 + ch * 16, Arows[row] + ko + ch * 8);
        }
#pragma unroll
        for (int i = 0; i < 2; i++) {
            int c = i * 256 + tid;
            int row = c >> 2, ch = c & 3;
            cp_async16s(bb + row * 80 + ch * 16,
                        Bexp + (size_t)(n0blk + row) * Kdim + ko + ch * 8);
        }
        cp_commit();
    };

    issue(0, 0);
    for (int kt = 0; kt < nk; ++kt) {
        int cur = kt & 1;
        if (kt + 1 < nk) { issue(cur ^ 1, kt + 1); cp_wait1(); }
        else             { cp_wait0(); }
        __syncthreads();

        const uint32_t* As32 = reinterpret_cast<const uint32_t*>(As[cur]);
        const uint32_t* Bs32 = reinterpret_cast<const uint32_t*>(Bs[cur]);

#pragma unroll
        for (int s = 0; s < 2; s++) {           // two k16 steps per stage
            const int ws = s * 8;
            uint32_t afr[4][4];
#pragma unroll
            for (int mi = 0; mi < 4; mi++) {
                int r = wm + mi * 16 + grp;
                const uint32_t* a0 = &As32[r * ROWW + ws + qid];
                const uint32_t* a1 = &As32[(r + 8) * ROWW + ws + qid];
                afr[mi][0] = a0[0];
                afr[mi][1] = a1[0];
                afr[mi][2] = a0[4];
                afr[mi][3] = a1[4];
            }
            uint32_t bfr[4][2];
#pragma unroll
            for (int ni = 0; ni < 4; ni++) {
                int n = wn + ni * 8 + grp;
                const uint32_t* b0 = &Bs32[n * ROWW + ws + qid];
                bfr[ni][0] = b0[0];
                bfr[ni][1] = b0[4];
            }
#pragma unroll
            for (int mi = 0; mi < 4; mi++)
#pragma unroll
                for (int ni = 0; ni < 4; ni++)
                    mma_f16(acc[mi][ni], afr[mi], bfr[ni]);
        }
        __syncthreads();
    }

    // ---------------- epilogue ----------------
#pragma unroll
    for (int mi = 0; mi < 4; mi++) {
        int r0 = m0blk + wm + mi * 16 + grp;
        int r1 = r0 + 8;
#pragma unroll
        for (int ni = 0; ni < 4; ni++) {
            int c0 = n0blk + wn + ni * 8 + qid * 2;
            float b0  = brow[c0];
            float b1v = brow[c0 + 1];
            float v00 = acc[mi][ni][0] + b0, v01 = acc[mi][ni][1] + b1v;
            float v10 = acc[mi][ni][2] + b0, v11 = acc[mi][ni][3] + b1v;
            if (EPI == 0) {
                size_t o0 = (size_t)(e * CAP + r0) * Ncols + c0;
                size_t o1 = (size_t)(e * CAP + r1) * Ncols + c0;
                *(__half2*)&g_hbufh[o0] = __floats2half2_rn(gelu_exact(v00), gelu_exact(v01));
                *(__half2*)&g_hbufh[o1] = __floats2half2_rn(gelu_exact(v10), gelu_exact(v11));
            } else {
                size_t o0 = (size_t)(e * CAP + r0) * Ncols + c0;
                size_t o1 = (size_t)(e * CAP + r1) * Ncols + c0;
                *(float2*)&g_obuf[o0] = make_float2(v00, v01);
                *(float2*)&g_obuf[o1] = make_float2(v10, v11);
            }
        }
    }
}

// ---------------- gated combine ----------------
__global__ __launch_bounds__(256) void combine_kernel(float* __restrict__ out)
{
    int idx = blockIdx.x * 256 + threadIdx.x;      // T*D/4 threads
    int t = idx >> 8;
    int c = (idx & 255) * 4;
    int sp0 = g_slotpos[2 * t], sp1 = g_slotpos[2 * t + 1];
    float g0 = g_gate[2 * t],  g1 = g_gate[2 * t + 1];
    float4 acc = make_float4(0.f, 0.f, 0.f, 0.f);
    if (sp0 >= 0) {
        float4 v = *(const float4*)&g_obuf[(size_t)sp0 * DDIM + c];
        acc.x += g0 * v.x; acc.y += g0 * v.y; acc.z += g0 * v.z; acc.w += g0 * v.w;
    }
    if (sp1 >= 0) {
        float4 v = *(const float4*)&g_obuf[(size_t)sp1 * DDIM + c];
        acc.x += g1 * v.x; acc.y += g1 * v.y; acc.z += g1 * v.z; acc.w += g1 * v.w;
    }
    *(float4*)&out[(size_t)t * DDIM + c] = acc;
}

// ---------------- launch ----------------
extern "C" void kernel_launch(void* const* d_in, const int* in_sizes, int n_in,
                              void* d_out, int out_size)
{
    (void)in_sizes; (void)n_in; (void)out_size;
    const float* x   = (const float*)d_in[0];
    const float* rw  = (const float*)d_in[1];
    const float* w1  = (const float*)d_in[2];
    const float* b1  = (const float*)d_in[3];
    const float* w2  = (const float*)d_in[4];
    const float* b2  = (const float*)d_in[5];
    float* out = (float*)d_out;

    __half *w1h_p, *w2h_p, *xh_p;
    cudaGetSymbolAddress((void**)&w1h_p, g_w1h);
    cudaGetSymbolAddress((void**)&w2h_p, g_w2h);
    cudaGetSymbolAddress((void**)&xh_p,  g_xh);

    // prep: transpose weights to [N][K] half; x to half
    dim3 tb(32, 8);
    transpose_h<<<dim3(HDIM / 32, DDIM / 32, NEXP), tb>>>(w1, w1h_p, DDIM, HDIM);
    transpose_h<<<dim3(DDIM / 32, HDIM / 32, NEXP), tb>>>(w2, w2h_p, HDIM, DDIM);
    cvt_h<<<512, 256>>>((const float2*)x, (__half2*)xh_p, (T_TOK * DDIM) / 2);

    router_kernel<<<T_TOK / 8, 256>>>(x, rw);
    scan_kernel<<<1, 256>>>(out + (size_t)T_TOK * DDIM);

    moe_gemm_h<0><<<dim3(HDIM / BN, CAP / BM, NEXP), 256>>>(w1h_p, b1, DDIM, HDIM);
    moe_gemm_h<1><<<dim3(DDIM / BN, CAP / BM, NEXP), 256>>>(w2h_p, b2, HDIM, DDIM);

    combine_kernel<<<(T_TOK * DDIM / 4) / 256, 256>>>(out);
}